// round 7
// baseline (speedup 1.0000x reference)
#include <cuda_runtime.h>
#include <cuda_fp16.h>
#include <math.h>

#define BB 64
#define TT 512
#define NN 256
#define DD 128
#define LOG_2PI_F 1.8378770664093453f

// ---------------- device scratch (static globals; no allocs) ----------------
static __device__ float   E_sc[BB * TT * NN];          // emission logprobs [B*T, N] fp32
static __device__ __half2 AhT_g[(NN / 2) * NN];        // packed A^T: [k][j] = (A[2k][j], A[2k+1][j])
static __device__ __half2 WpT_g[DD * NN];              // [d][n] = (-0.5*iv, mu*iv) as half2
static __device__ float   cvec_g[NN];                  // -0.5 * sum_d (mu^2*iv + log_var + LOG2PI)
static __device__ float   logpi_g[NN];
static __device__ float   logprop_g[BB];

// order-preserving float<->uint map for REDUX-based fp max.
__device__ __forceinline__ float warp_max_f(float x) {
    unsigned u = __float_as_uint(x);
    u = ((int)u >= 0) ? (u ^ 0x80000000u) : ~u;
    u = __reduce_max_sync(0xffffffffu, u);
    return ((int)u < 0) ? __uint_as_float(u ^ 0x80000000u) : __uint_as_float(~u);
}

// ---------------- merged prep kernel (unchanged from passing R5) ----------------
__global__ void prep_all(const float* __restrict__ trans, const float* __restrict__ pri,
                         const float* __restrict__ mu, const float* __restrict__ lv) {
    __shared__ float redA[8], redB[8];
    int bid = blockIdx.x, t = threadIdx.x;
    int wid = t >> 5, lane = t & 31;

    if (bid < 128) {
        int k = bid;
        float v0 = trans[(2 * k) * NN + t];
        float v1 = trans[(2 * k + 1) * NN + t];
        float m0 = v0, m1 = v1;
#pragma unroll
        for (int o = 16; o; o >>= 1) {
            m0 = fmaxf(m0, __shfl_xor_sync(0xffffffffu, m0, o));
            m1 = fmaxf(m1, __shfl_xor_sync(0xffffffffu, m1, o));
        }
        if (lane == 0) { redA[wid] = m0; redB[wid] = m1; }
        __syncthreads();
        float mb0 = redA[0], mb1 = redB[0];
#pragma unroll
        for (int w = 1; w < 8; w++) { mb0 = fmaxf(mb0, redA[w]); mb1 = fmaxf(mb1, redB[w]); }
        __syncthreads();
        float e0 = expf(v0 - mb0), e1 = expf(v1 - mb1);
        float s0 = e0, s1 = e1;
#pragma unroll
        for (int o = 16; o; o >>= 1) {
            s0 += __shfl_xor_sync(0xffffffffu, s0, o);
            s1 += __shfl_xor_sync(0xffffffffu, s1, o);
        }
        if (lane == 0) { redA[wid] = s0; redB[wid] = s1; }
        __syncthreads();
        float S0 = 0.f, S1 = 0.f;
#pragma unroll
        for (int w = 0; w < 8; w++) { S0 += redA[w]; S1 += redB[w]; }
        AhT_g[k * NN + t] = __floats2half2_rn(e0 / S0, e1 / S1);
    } else if (bid == 128) {
        float v = pri[t];
        float m = v;
#pragma unroll
        for (int o = 16; o; o >>= 1) m = fmaxf(m, __shfl_xor_sync(0xffffffffu, m, o));
        if (lane == 0) redA[wid] = m;
        __syncthreads();
        float mb = redA[0];
#pragma unroll
        for (int w = 1; w < 8; w++) mb = fmaxf(mb, redA[w]);
        __syncthreads();
        float e = expf(v - mb);
        float s = e;
#pragma unroll
        for (int o = 16; o; o >>= 1) s += __shfl_xor_sync(0xffffffffu, s, o);
        if (lane == 0) redA[wid] = s;
        __syncthreads();
        float S = 0.f;
#pragma unroll
        for (int w = 0; w < 8; w++) S += redA[w];
        logpi_g[t] = (v - mb) - logf(S);
    } else {
        int wb = bid - 129;
        int n = 2 * wb + (t >> 7);
        int d = t & 127;
        float l = lv[n * DD + d];
        float m = mu[n * DD + d];
        float iv = expf(-l);
        WpT_g[d * NN + n] = __floats2half2_rn(-0.5f * iv, m * iv);
        float c = m * m * iv + l + LOG_2PI_F;
#pragma unroll
        for (int o = 16; o; o >>= 1) c += __shfl_xor_sync(0xffffffffu, c, o);
        if (lane == 0) redA[wid] = c;
        __syncthreads();
        if ((t & 127) == 0) {
            int base = (t >> 7) * 4;
            float s = redA[base] + redA[base + 1] + redA[base + 2] + redA[base + 3];
            cvec_g[n] = -0.5f * s;
        }
    }
}

// ---------------- emission GEMM, register-tiled ----------------
// thread: ib = tid&3 (d-range [32*ib, 32*ib+32)), nb = tid>>2 (4 n-cols 4nb..4nb+3).
// After quad xor-reduce, lane keeps S_{ib}; its output state n = 4*nb+ib = tid.
__global__ void __launch_bounds__(256, 1) emis_kernel(const float* __restrict__ X) {
    __shared__ __align__(16) __half2 xp[32 * DD];      // (x^2, x) per [m][d], 16 KB
    int tid = threadIdx.x;
    int r0 = blockIdx.x * 32;
    int ib = tid & 3, nb = tid >> 2;

#pragma unroll
    for (int it = 0; it < 16; it++) {
        int idx = it * 256 + tid;
        int m = idx >> 7, d = idx & 127;
        float x = X[(r0 + m) * DD + d];
        xp[idx] = __floats2half2_rn(x * x, x);
    }

    // W tile: w2[c][k] for n = 4nb+c, d = 32*ib+k
    __half2 w2[4][32];
#pragma unroll
    for (int c = 0; c < 4; c++)
#pragma unroll
        for (int k = 0; k < 32; k++)
            w2[c][k] = WpT_g[(32 * ib + k) * NN + 4 * nb + c];
    float cn = cvec_g[tid];                            // final state = tid
    __syncthreads();

    for (int m = 0; m < 32; m++) {
        const float4* xr = reinterpret_cast<const float4*>(xp + m * DD + 32 * ib); // 8 float4
        __half2 a0 = __float2half2_rn(0.f), a1 = a0, a2 = a0, a3 = a0;
#pragma unroll
        for (int q = 0; q < 8; q++) {
            float4 v = xr[q];
            const __half2* xv = reinterpret_cast<const __half2*>(&v);
#pragma unroll
            for (int h = 0; h < 4; h++) {
                a0 = __hfma2(w2[0][4 * q + h], xv[h], a0);
                a1 = __hfma2(w2[1][4 * q + h], xv[h], a1);
                a2 = __hfma2(w2[2][4 * q + h], xv[h], a2);
                a3 = __hfma2(w2[3][4 * q + h], xv[h], a3);
            }
        }
        float2 f0 = __half22float2(a0), f1 = __half22float2(a1);
        float2 f2 = __half22float2(a2), f3 = __half22float2(a3);
        float S0 = f0.x + f0.y, S1 = f1.x + f1.y, S2 = f2.x + f2.y, S3 = f3.x + f3.y;
        // quad reduce over d-splits
        S0 += __shfl_xor_sync(0xffffffffu, S0, 1); S0 += __shfl_xor_sync(0xffffffffu, S0, 2);
        S1 += __shfl_xor_sync(0xffffffffu, S1, 1); S1 += __shfl_xor_sync(0xffffffffu, S1, 2);
        S2 += __shfl_xor_sync(0xffffffffu, S2, 1); S2 += __shfl_xor_sync(0xffffffffu, S2, 2);
        S3 += __shfl_xor_sync(0xffffffffu, S3, 1); S3 += __shfl_xor_sync(0xffffffffu, S3, 2);
        float S = (ib & 2) ? ((ib & 1) ? S3 : S2) : ((ib & 1) ? S1 : S0);
        E_sc[(r0 + m) * NN + tid] = S + cn;            // coalesced over tid
    }
}

// ---------------- forward recursion, register-tiled matvec ----------------
// thread: ib = tid&3 (i-range [64*ib, 64*ib+64)), jb = tid>>2 (4 j-cols 4jb..4jb+3).
// After quad xor-reduce, lane keeps S_{ib}; epilogue state j = 4*jb+ib = tid.
__global__ void __launch_bounds__(256, 1) forward_rec() {
    __shared__ __align__(16) __half psm[NN];
    __shared__ __align__(16) float red[8];
    int b = blockIdx.x, tid = threadIdx.x;
    int wid = tid >> 5, lane = tid & 31;
    int ib = tid & 3, jb = tid >> 2;

    // A tile: a2[c][k] = (A[64ib+2k][4jb+c], A[64ib+2k+1][4jb+c])
    __half2 a2[4][32];
#pragma unroll
    for (int c = 0; c < 4; c++)
#pragma unroll
        for (int k = 0; k < 32; k++)
            a2[c][k] = AhT_g[(32 * ib + k) * NN + 4 * jb + c];

    const float* __restrict__ Erow = E_sc + b * TT * NN;

    // alpha0 (state = tid)
    float alpha = logpi_g[tid] + Erow[tid];
    float m0 = warp_max_f(alpha);
    if (lane == 0) red[wid] = m0;
    __syncthreads();
    float4 ra = *reinterpret_cast<const float4*>(red);
    float4 rb = *reinterpret_cast<const float4*>(red + 4);
    float mprev = fmaxf(fmaxf(fmaxf(ra.x, ra.y), fmaxf(ra.z, ra.w)),
                        fmaxf(fmaxf(rb.x, rb.y), fmaxf(rb.z, rb.w)));
    float p = __expf(alpha - mprev);
    psm[tid] = __float2half(p);
    float e_next = Erow[1 * NN + tid];
    __syncthreads();

    for (int t = 1; t < TT; t++) {
        float em = e_next + mprev;
        if (t + 1 < TT) e_next = Erow[(t + 1) * NN + tid];

        // matvec partials over i-range [64ib, 64ib+64)
        const float4* p4 = reinterpret_cast<const float4*>(psm + 64 * ib);   // 8 float4
        __half2 a0 = __float2half2_rn(0.f), a1 = a0, a2r = a0, a3 = a0;
#pragma unroll
        for (int q = 0; q < 8; q++) {
            float4 v = p4[q];
            const __half2* pv = reinterpret_cast<const __half2*>(&v);
#pragma unroll
            for (int h = 0; h < 4; h++) {
                a0  = __hfma2(a2[0][4 * q + h], pv[h], a0);
                a1  = __hfma2(a2[1][4 * q + h], pv[h], a1);
                a2r = __hfma2(a2[2][4 * q + h], pv[h], a2r);
                a3  = __hfma2(a2[3][4 * q + h], pv[h], a3);
            }
        }
        float2 f0 = __half22float2(a0), f1 = __half22float2(a1);
        float2 f2 = __half22float2(a2r), f3 = __half22float2(a3);
        float S0 = f0.x + f0.y, S1 = f1.x + f1.y, S2 = f2.x + f2.y, S3 = f3.x + f3.y;
        // quad reduce over i-splits
        S0 += __shfl_xor_sync(0xffffffffu, S0, 1); S0 += __shfl_xor_sync(0xffffffffu, S0, 2);
        S1 += __shfl_xor_sync(0xffffffffu, S1, 1); S1 += __shfl_xor_sync(0xffffffffu, S1, 2);
        S2 += __shfl_xor_sync(0xffffffffu, S2, 1); S2 += __shfl_xor_sync(0xffffffffu, S2, 2);
        S3 += __shfl_xor_sync(0xffffffffu, S3, 1); S3 += __shfl_xor_sync(0xffffffffu, S3, 2);
        float S = (ib & 2) ? ((ib & 1) ? S3 : S2) : ((ib & 1) ? S1 : S0);

        float na = em + __logf(S);

        // block max: REDUX warp max + float4 cross-warp tree
        float mm = warp_max_f(na);
        if (lane == 0) red[wid] = mm;
        __syncthreads();                                 // fences matvec reads of psm
        float4 r0 = *reinterpret_cast<const float4*>(red);
        float4 r1 = *reinterpret_cast<const float4*>(red + 4);
        float mnew = fmaxf(fmaxf(fmaxf(r0.x, r0.y), fmaxf(r0.z, r0.w)),
                           fmaxf(fmaxf(r1.x, r1.y), fmaxf(r1.z, r1.w)));

        p = __expf(na - mnew);
        psm[tid] = __float2half(p);
        mprev = mnew;
        __syncthreads();                                 // psm ready for next step
    }

    float s = p;
#pragma unroll
    for (int o = 16; o; o >>= 1) s += __shfl_xor_sync(0xffffffffu, s, o);
    if (lane == 0) red[wid] = s;
    __syncthreads();
    if (tid == 0) {
        float tot = 0.f;
#pragma unroll
        for (int w = 0; w < 8; w++) tot += red[w];
        logprop_g[b] = mprev + __logf(tot);
    }
}

// ---------------- final: sum log_props over batch ----------------
__global__ void finalize_kernel(float* __restrict__ out) {
    __shared__ float red[2];
    int t = threadIdx.x;
    float v = logprop_g[t];
#pragma unroll
    for (int o = 16; o; o >>= 1) v += __shfl_xor_sync(0xffffffffu, v, o);
    if ((t & 31) == 0) red[t >> 5] = v;
    __syncthreads();
    if (t == 0) out[0] = red[0] + red[1];
}

// ---------------- launch ----------------
extern "C" void kernel_launch(void* const* d_in, const int* in_sizes, int n_in,
                              void* d_out, int out_size) {
    (void)in_sizes; (void)n_in; (void)out_size;
    const float* X     = (const float*)d_in[0];
    const float* mu    = (const float*)d_in[1];
    const float* lv    = (const float*)d_in[2];
    const float* trans = (const float*)d_in[3];
    const float* pri   = (const float*)d_in[4];
    float* out = (float*)d_out;

    prep_all<<<257, 256>>>(trans, pri, mu, lv);
    emis_kernel<<<(BB * TT) / 32, 256>>>(X);
    forward_rec<<<BB, 256>>>();
    finalize_kernel<<<1, 64>>>(out);
}

// round 8
// speedup vs baseline: 1.2690x; 1.2690x over previous
#include <cuda_runtime.h>
#include <cuda_fp16.h>
#include <math.h>

#define BB 64
#define TT 512
#define NN 256
#define DD 128
#define LOG_2PI_F 1.8378770664093453f

// ---------------- device scratch (static globals; no allocs) ----------------
static __device__ float   E_sc[BB * TT * NN];          // emission logprobs [B*T, N] fp32
static __device__ __half2 AhT_g[(NN / 2) * NN];        // packed A^T: [k][j] = (A[2k][j], A[2k+1][j])
static __device__ __half2 WpT_g[DD * NN];              // [d][n] = (-0.5*iv, mu*iv) as half2
static __device__ float   cvec_g[NN];                  // -0.5 * sum_d (mu^2*iv + log_var + LOG2PI)
static __device__ float   logpi_g[NN];
static __device__ float   logprop_g[BB];

// order-preserving float<->uint map for REDUX-based fp max.
__device__ __forceinline__ float warp_max_f(float x) {
    unsigned u = __float_as_uint(x);
    u = ((int)u >= 0) ? (u ^ 0x80000000u) : ~u;
    u = __reduce_max_sync(0xffffffffu, u);
    return ((int)u < 0) ? __uint_as_float(u ^ 0x80000000u) : __uint_as_float(~u);
}

// ---------------- merged prep kernel (unchanged, proven) ----------------
__global__ void prep_all(const float* __restrict__ trans, const float* __restrict__ pri,
                         const float* __restrict__ mu, const float* __restrict__ lv) {
    __shared__ float redA[8], redB[8];
    int bid = blockIdx.x, t = threadIdx.x;
    int wid = t >> 5, lane = t & 31;

    if (bid < 128) {
        int k = bid;
        float v0 = trans[(2 * k) * NN + t];
        float v1 = trans[(2 * k + 1) * NN + t];
        float m0 = v0, m1 = v1;
#pragma unroll
        for (int o = 16; o; o >>= 1) {
            m0 = fmaxf(m0, __shfl_xor_sync(0xffffffffu, m0, o));
            m1 = fmaxf(m1, __shfl_xor_sync(0xffffffffu, m1, o));
        }
        if (lane == 0) { redA[wid] = m0; redB[wid] = m1; }
        __syncthreads();
        float mb0 = redA[0], mb1 = redB[0];
#pragma unroll
        for (int w = 1; w < 8; w++) { mb0 = fmaxf(mb0, redA[w]); mb1 = fmaxf(mb1, redB[w]); }
        __syncthreads();
        float e0 = expf(v0 - mb0), e1 = expf(v1 - mb1);
        float s0 = e0, s1 = e1;
#pragma unroll
        for (int o = 16; o; o >>= 1) {
            s0 += __shfl_xor_sync(0xffffffffu, s0, o);
            s1 += __shfl_xor_sync(0xffffffffu, s1, o);
        }
        if (lane == 0) { redA[wid] = s0; redB[wid] = s1; }
        __syncthreads();
        float S0 = 0.f, S1 = 0.f;
#pragma unroll
        for (int w = 0; w < 8; w++) { S0 += redA[w]; S1 += redB[w]; }
        AhT_g[k * NN + t] = __floats2half2_rn(e0 / S0, e1 / S1);
    } else if (bid == 128) {
        float v = pri[t];
        float m = v;
#pragma unroll
        for (int o = 16; o; o >>= 1) m = fmaxf(m, __shfl_xor_sync(0xffffffffu, m, o));
        if (lane == 0) redA[wid] = m;
        __syncthreads();
        float mb = redA[0];
#pragma unroll
        for (int w = 1; w < 8; w++) mb = fmaxf(mb, redA[w]);
        __syncthreads();
        float e = expf(v - mb);
        float s = e;
#pragma unroll
        for (int o = 16; o; o >>= 1) s += __shfl_xor_sync(0xffffffffu, s, o);
        if (lane == 0) redA[wid] = s;
        __syncthreads();
        float S = 0.f;
#pragma unroll
        for (int w = 0; w < 8; w++) S += redA[w];
        logpi_g[t] = (v - mb) - logf(S);
    } else {
        int wb = bid - 129;
        int n = 2 * wb + (t >> 7);
        int d = t & 127;
        float l = lv[n * DD + d];
        float m = mu[n * DD + d];
        float iv = expf(-l);
        WpT_g[d * NN + n] = __floats2half2_rn(-0.5f * iv, m * iv);
        float c = m * m * iv + l + LOG_2PI_F;
#pragma unroll
        for (int o = 16; o; o >>= 1) c += __shfl_xor_sync(0xffffffffu, c, o);
        if (lane == 0) redA[wid] = c;
        __syncthreads();
        if ((t & 127) == 0) {
            int base = (t >> 7) * 4;
            float s = redA[base] + redA[base + 1] + redA[base + 2] + redA[base + 3];
            cvec_g[n] = -0.5f * s;
        }
    }
}

// ---------------- emission GEMM, c=2 column-blocked ----------------
// thread: ib = tid&1 (d-range [64*ib, 64*ib+64)), nb = tid>>1 (cols 2nb, 2nb+1).
// After 1 xor-shuffle per col, lane keeps col 2nb+ib = tid.
__global__ void __launch_bounds__(256, 1) emis_kernel(const float* __restrict__ X) {
    __shared__ __align__(16) __half2 xp[32 * DD];      // (x^2, x) per [m][d], 16 KB
    int tid = threadIdx.x;
    int r0 = blockIdx.x * 32;
    int ib = tid & 1, nb = tid >> 1;

#pragma unroll
    for (int it = 0; it < 16; it++) {
        int idx = it * 256 + tid;
        int m = idx >> 7, d = idx & 127;
        float x = X[(r0 + m) * DD + d];
        xp[idx] = __floats2half2_rn(x * x, x);
    }

    // flat W tiles: w0/w1 for cols 2nb, 2nb+1; d = 64*ib + k
    __half2 w0[64], w1[64];
#pragma unroll
    for (int k = 0; k < 64; k++) {
        w0[k] = WpT_g[(64 * ib + k) * NN + 2 * nb];
        w1[k] = WpT_g[(64 * ib + k) * NN + 2 * nb + 1];
    }
    float cn = cvec_g[tid];                            // final state = tid
    __syncthreads();

    for (int m = 0; m < 32; m++) {
        const float4* xr = reinterpret_cast<const float4*>(xp + m * DD + 64 * ib); // 16 float4
        __half2 c0a = __float2half2_rn(0.f), c0b = c0a, c1a = c0a, c1b = c0a;
#pragma unroll
        for (int q = 0; q < 16; q++) {
            float4 v = xr[q];
            const __half2* xv = reinterpret_cast<const __half2*>(&v);
            c0a = __hfma2(w0[4 * q + 0], xv[0], c0a);
            c1a = __hfma2(w1[4 * q + 0], xv[0], c1a);
            c0b = __hfma2(w0[4 * q + 1], xv[1], c0b);
            c1b = __hfma2(w1[4 * q + 1], xv[1], c1b);
            c0a = __hfma2(w0[4 * q + 2], xv[2], c0a);
            c1a = __hfma2(w1[4 * q + 2], xv[2], c1a);
            c0b = __hfma2(w0[4 * q + 3], xv[3], c0b);
            c1b = __hfma2(w1[4 * q + 3], xv[3], c1b);
        }
        float2 f0 = __half22float2(__hadd2(c0a, c0b));
        float2 f1 = __half22float2(__hadd2(c1a, c1b));
        float S0 = f0.x + f0.y, S1 = f1.x + f1.y;
        S0 += __shfl_xor_sync(0xffffffffu, S0, 1);     // combine d-halves
        S1 += __shfl_xor_sync(0xffffffffu, S1, 1);
        float S = ib ? S1 : S0;
        E_sc[(r0 + m) * NN + tid] = S + cn;            // coalesced over tid
    }
}

// ---------------- forward recursion, c=2 column-blocked matvec ----------------
// thread: ib = tid&1 (i-range [128*ib, 128*ib+128)), jb = tid>>1 (cols 2jb, 2jb+1).
// After 1 xor-shuffle per col, lane keeps col 2jb+ib = tid; epilogue unchanged.
__global__ void __launch_bounds__(256, 1) forward_rec() {
    __shared__ __align__(16) __half psm[NN];
    __shared__ __align__(16) float red[8];
    int b = blockIdx.x, tid = threadIdx.x;
    int wid = tid >> 5, lane = tid & 31;
    int ib = tid & 1, jb = tid >> 1;

    // flat A tiles: pair index k covers i = 128*ib + 2k, 2k+1
    __half2 a0[64], a1[64];
#pragma unroll
    for (int k = 0; k < 64; k++) {
        a0[k] = AhT_g[(64 * ib + k) * NN + 2 * jb];
        a1[k] = AhT_g[(64 * ib + k) * NN + 2 * jb + 1];
    }

    const float* __restrict__ Erow = E_sc + b * TT * NN;

    // alpha0 (state = tid)
    float alpha = logpi_g[tid] + Erow[tid];
    float m0 = warp_max_f(alpha);
    if (lane == 0) red[wid] = m0;
    __syncthreads();
    float4 ra = *reinterpret_cast<const float4*>(red);
    float4 rb = *reinterpret_cast<const float4*>(red + 4);
    float mprev = fmaxf(fmaxf(fmaxf(ra.x, ra.y), fmaxf(ra.z, ra.w)),
                        fmaxf(fmaxf(rb.x, rb.y), fmaxf(rb.z, rb.w)));
    float p = __expf(alpha - mprev);
    psm[tid] = __float2half(p);
    float e_next = Erow[1 * NN + tid];
    __syncthreads();

    for (int t = 1; t < TT; t++) {
        float em = e_next + mprev;
        if (t + 1 < TT) e_next = Erow[(t + 1) * NN + tid];

        // matvec partials over i-range [128*ib, 128*ib+128)  (16 float4 = 256B)
        const float4* p4 = reinterpret_cast<const float4*>(psm + 128 * ib);
        __half2 c0a = __float2half2_rn(0.f), c0b = c0a, c1a = c0a, c1b = c0a;
#pragma unroll
        for (int q = 0; q < 16; q++) {
            float4 v = p4[q];
            const __half2* pv = reinterpret_cast<const __half2*>(&v);
            c0a = __hfma2(a0[4 * q + 0], pv[0], c0a);
            c1a = __hfma2(a1[4 * q + 0], pv[0], c1a);
            c0b = __hfma2(a0[4 * q + 1], pv[1], c0b);
            c1b = __hfma2(a1[4 * q + 1], pv[1], c1b);
            c0a = __hfma2(a0[4 * q + 2], pv[2], c0a);
            c1a = __hfma2(a1[4 * q + 2], pv[2], c1a);
            c0b = __hfma2(a0[4 * q + 3], pv[3], c0b);
            c1b = __hfma2(a1[4 * q + 3], pv[3], c1b);
        }
        float2 f0 = __half22float2(__hadd2(c0a, c0b));
        float2 f1 = __half22float2(__hadd2(c1a, c1b));
        float S0 = f0.x + f0.y, S1 = f1.x + f1.y;
        S0 += __shfl_xor_sync(0xffffffffu, S0, 1);     // combine i-halves
        S1 += __shfl_xor_sync(0xffffffffu, S1, 1);
        float S = ib ? S1 : S0;

        float na = em + __logf(S);

        // block max: REDUX warp max + float4 cross-warp tree
        float mm = warp_max_f(na);
        if (lane == 0) red[wid] = mm;
        __syncthreads();                                 // fences matvec reads of psm
        float4 r0 = *reinterpret_cast<const float4*>(red);
        float4 r1 = *reinterpret_cast<const float4*>(red + 4);
        float mnew = fmaxf(fmaxf(fmaxf(r0.x, r0.y), fmaxf(r0.z, r0.w)),
                           fmaxf(fmaxf(r1.x, r1.y), fmaxf(r1.z, r1.w)));

        p = __expf(na - mnew);
        psm[tid] = __float2half(p);
        mprev = mnew;
        __syncthreads();                                 // psm ready for next step
    }

    float s = p;
#pragma unroll
    for (int o = 16; o; o >>= 1) s += __shfl_xor_sync(0xffffffffu, s, o);
    if (lane == 0) red[wid] = s;
    __syncthreads();
    if (tid == 0) {
        float tot = 0.f;
#pragma unroll
        for (int w = 0; w < 8; w++) tot += red[w];
        logprop_g[b] = mprev + __logf(tot);
    }
}

// ---------------- final: sum log_props over batch ----------------
__global__ void finalize_kernel(float* __restrict__ out) {
    __shared__ float red[2];
    int t = threadIdx.x;
    float v = logprop_g[t];
#pragma unroll
    for (int o = 16; o; o >>= 1) v += __shfl_xor_sync(0xffffffffu, v, o);
    if ((t & 31) == 0) red[t >> 5] = v;
    __syncthreads();
    if (t == 0) out[0] = red[0] + red[1];
}

// ---------------- launch ----------------
extern "C" void kernel_launch(void* const* d_in, const int* in_sizes, int n_in,
                              void* d_out, int out_size) {
    (void)in_sizes; (void)n_in; (void)out_size;
    const float* X     = (const float*)d_in[0];
    const float* mu    = (const float*)d_in[1];
    const float* lv    = (const float*)d_in[2];
    const float* trans = (const float*)d_in[3];
    const float* pri   = (const float*)d_in[4];
    float* out = (float*)d_out;

    prep_all<<<257, 256>>>(trans, pri, mu, lv);
    emis_kernel<<<(BB * TT) / 32, 256>>>(X);
    forward_rec<<<BB, 256>>>();
    finalize_kernel<<<1, 64>>>(out);
}

// round 11
// speedup vs baseline: 1.7231x; 1.3579x over previous
#include <cuda_runtime.h>
#include <cuda_fp16.h>
#include <cuda_bf16.h>
#include <math.h>

#define BB 64
#define TT 512
#define NN 256
#define DD 128
#define LOG_2PI_F 1.8378770664093453f
#define LN2_F 0.6931471805599453f

// ---------------- device scratch (static globals; no allocs) ----------------
static __device__ float          E_sc[BB * TT * NN];   // emission logprobs [B*T, N] fp32 (unshifted)
static __device__ float          M_sc[BB * TT];        // per-row max of E
static __device__ __nv_bfloat162 AhT_g[(NN / 2) * NN]; // packed A^T bf16: [k][j] = (A[2k][j], A[2k+1][j])
static __device__ __half2        WpT_g[DD * NN];       // [d][n] = (-0.5*iv, mu*iv) as half2
static __device__ float          cvec_g[NN];           // -0.5 * sum_d (mu^2*iv + log_var + LOG2PI)
static __device__ float          logpi_g[NN];
static __device__ float          logprop_g[BB];

// order-preserving float<->uint map for REDUX-based fp max (handles negatives)
__device__ __forceinline__ float warp_max_f(float x) {
    unsigned u = __float_as_uint(x);
    u = ((int)u >= 0) ? (u ^ 0x80000000u) : ~u;
    u = __reduce_max_sync(0xffffffffu, u);
    return ((int)u < 0) ? __uint_as_float(u ^ 0x80000000u) : __uint_as_float(~u);
}

// ---------------- merged prep kernel ----------------
__global__ void prep_all(const float* __restrict__ trans, const float* __restrict__ pri,
                         const float* __restrict__ mu, const float* __restrict__ lv) {
    __shared__ float redA[8], redB[8];
    int bid = blockIdx.x, t = threadIdx.x;
    int wid = t >> 5, lane = t & 31;

    if (bid < 128) {
        int k = bid;
        float v0 = trans[(2 * k) * NN + t];
        float v1 = trans[(2 * k + 1) * NN + t];
        float m0 = v0, m1 = v1;
#pragma unroll
        for (int o = 16; o; o >>= 1) {
            m0 = fmaxf(m0, __shfl_xor_sync(0xffffffffu, m0, o));
            m1 = fmaxf(m1, __shfl_xor_sync(0xffffffffu, m1, o));
        }
        if (lane == 0) { redA[wid] = m0; redB[wid] = m1; }
        __syncthreads();
        float mb0 = redA[0], mb1 = redB[0];
#pragma unroll
        for (int w = 1; w < 8; w++) { mb0 = fmaxf(mb0, redA[w]); mb1 = fmaxf(mb1, redB[w]); }
        __syncthreads();
        float e0 = expf(v0 - mb0), e1 = expf(v1 - mb1);
        float s0 = e0, s1 = e1;
#pragma unroll
        for (int o = 16; o; o >>= 1) {
            s0 += __shfl_xor_sync(0xffffffffu, s0, o);
            s1 += __shfl_xor_sync(0xffffffffu, s1, o);
        }
        if (lane == 0) { redA[wid] = s0; redB[wid] = s1; }
        __syncthreads();
        float S0 = 0.f, S1 = 0.f;
#pragma unroll
        for (int w = 0; w < 8; w++) { S0 += redA[w]; S1 += redB[w]; }
        AhT_g[k * NN + t] = __floats2bfloat162_rn(e0 / S0, e1 / S1);
    } else if (bid == 128) {
        float v = pri[t];
        float m = v;
#pragma unroll
        for (int o = 16; o; o >>= 1) m = fmaxf(m, __shfl_xor_sync(0xffffffffu, m, o));
        if (lane == 0) redA[wid] = m;
        __syncthreads();
        float mb = redA[0];
#pragma unroll
        for (int w = 1; w < 8; w++) mb = fmaxf(mb, redA[w]);
        __syncthreads();
        float e = expf(v - mb);
        float s = e;
#pragma unroll
        for (int o = 16; o; o >>= 1) s += __shfl_xor_sync(0xffffffffu, s, o);
        if (lane == 0) redA[wid] = s;
        __syncthreads();
        float S = 0.f;
#pragma unroll
        for (int w = 0; w < 8; w++) S += redA[w];
        logpi_g[t] = (v - mb) - logf(S);
    } else {
        int wb = bid - 129;
        int n = 2 * wb + (t >> 7);
        int d = t & 127;
        float l = lv[n * DD + d];
        float m = mu[n * DD + d];
        float iv = expf(-l);
        WpT_g[d * NN + n] = __floats2half2_rn(-0.5f * iv, m * iv);
        float c = m * m * iv + l + LOG_2PI_F;
#pragma unroll
        for (int o = 16; o; o >>= 1) c += __shfl_xor_sync(0xffffffffu, c, o);
        if (lane == 0) redA[wid] = c;
        __syncthreads();
        if ((t & 127) == 0) {
            int base = (t >> 7) * 4;
            float s = redA[base] + redA[base + 1] + redA[base + 2] + redA[base + 3];
            cvec_g[n] = -0.5f * s;
        }
    }
}

// ---------------- emission GEMM (R8 structure) + row-max epilogue ----------------
// thread: ib = tid&1 (d-range [64*ib, 64*ib+64)), nb = tid>>1 (cols 2nb, 2nb+1).
__global__ void __launch_bounds__(256, 1) emis_kernel(const float* __restrict__ X) {
    __shared__ __align__(16) __half2 xp[32 * DD];      // (x^2, x) per [m][d], 16 KB
    __shared__ __align__(16) float redM[32][8];        // per-row warp maxes
    int tid = threadIdx.x;
    int r0 = blockIdx.x * 32;
    int ib = tid & 1, nb = tid >> 1;
    int wid = tid >> 5, lane = tid & 31;

#pragma unroll
    for (int it = 0; it < 16; it++) {
        int idx = it * 256 + tid;
        int m = idx >> 7, d = idx & 127;
        float x = X[(r0 + m) * DD + d];
        xp[idx] = __floats2half2_rn(x * x, x);
    }

    __half2 w0[64], w1[64];
#pragma unroll
    for (int k = 0; k < 64; k++) {
        w0[k] = WpT_g[(64 * ib + k) * NN + 2 * nb];
        w1[k] = WpT_g[(64 * ib + k) * NN + 2 * nb + 1];
    }
    float cn = cvec_g[tid];
    __syncthreads();

    for (int m = 0; m < 32; m++) {
        const float4* xr = reinterpret_cast<const float4*>(xp + m * DD + 64 * ib);
        __half2 c0a = __float2half2_rn(0.f), c0b = c0a, c1a = c0a, c1b = c0a;
#pragma unroll
        for (int q = 0; q < 16; q++) {
            float4 v = xr[q];
            const __half2* xv = reinterpret_cast<const __half2*>(&v);
            c0a = __hfma2(w0[4 * q + 0], xv[0], c0a);
            c1a = __hfma2(w1[4 * q + 0], xv[0], c1a);
            c0b = __hfma2(w0[4 * q + 1], xv[1], c0b);
            c1b = __hfma2(w1[4 * q + 1], xv[1], c1b);
            c0a = __hfma2(w0[4 * q + 2], xv[2], c0a);
            c1a = __hfma2(w1[4 * q + 2], xv[2], c1a);
            c0b = __hfma2(w0[4 * q + 3], xv[3], c0b);
            c1b = __hfma2(w1[4 * q + 3], xv[3], c1b);
        }
        float2 f0 = __half22float2(__hadd2(c0a, c0b));
        float2 f1 = __half22float2(__hadd2(c1a, c1b));
        float S0 = f0.x + f0.y, S1 = f1.x + f1.y;
        S0 += __shfl_xor_sync(0xffffffffu, S0, 1);
        S1 += __shfl_xor_sync(0xffffffffu, S1, 1);
        float val = (ib ? S1 : S0) + cn;
        E_sc[(r0 + m) * NN + tid] = val;               // coalesced over tid
        float mm = warp_max_f(val);                    // warp REDUX, no barrier
        if (lane == 0) redM[m][wid] = mm;
    }
    __syncthreads();
    if (tid < 32) {
        float4 q0 = *reinterpret_cast<const float4*>(&redM[tid][0]);
        float4 q1 = *reinterpret_cast<const float4*>(&redM[tid][4]);
        float M = fmaxf(fmaxf(fmaxf(q0.x, q0.y), fmaxf(q0.z, q0.w)),
                        fmaxf(fmaxf(q1.x, q1.y), fmaxf(q1.z, q1.w)));
        M_sc[r0 + tid] = M;
    }
}

// ---------------- forward recursion: deterministic normalization ----------------
// p_j(t) = exp(E[t,j] - M[t]) * S_j,  S_j = sum_i p_i(t-1) A_ij,  mhat += M[t].
// No per-step max/log; ONE barrier per step (double-buffered p in bf16).
// Exponent-only renorm staged at t=0,4,8,... (warp REDUX, lane0 -> redu),
// applied exactly (power of two) at t=1,5,9,...; mhat absorbs e2*ln2.
__global__ void __launch_bounds__(256, 1) forward_rec() {
    __shared__ __align__(16) __nv_bfloat16 psm[2 * NN];
    __shared__ __align__(16) unsigned redu[8];
    __shared__ float red[8];
    int b = blockIdx.x, tid = threadIdx.x;
    int wid = tid >> 5, lane = tid & 31;
    int ib = tid & 1, jb = tid >> 1;

    // A tiles (bf16): pair index k covers i = 128*ib + 2k, 2k+1; cols 2jb, 2jb+1
    __nv_bfloat162 a0[64], a1[64];
#pragma unroll
    for (int k = 0; k < 64; k++) {
        a0[k] = AhT_g[(64 * ib + k) * NN + 2 * jb];
        a1[k] = AhT_g[(64 * ib + k) * NN + 2 * jb + 1];
    }

    const float* __restrict__ Erow = E_sc + b * TT * NN;
    const float* __restrict__ Mrow = M_sc + b * TT;

    // t = 0: p = exp(logpi + E0 - M0), mhat = M0. Stage renorm for t=1.
    float M0 = Mrow[0];
    float p = __expf(logpi_g[tid] + Erow[tid] - M0);
    float mhat = M0;
    psm[tid] = __float2bfloat16(p);                    // buffer 0
    {
        unsigned pb = __reduce_max_sync(0xffffffffu, __float_as_uint(p));
        if (lane == 0) redu[wid] = pb;                 // p > 0: bits compare as uint
    }
    int cur = 0;
    float e_next = Erow[1 * NN + tid];
    float Mn = Mrow[1];
    __syncthreads();                                   // orders psm + redu for t=1

    const __nv_bfloat162 bzero = __float2bfloat162_rn(0.f);

    for (int t = 1; t < TT; t++) {
        float e = e_next;
        float Mt = Mn;
        if (t + 1 < TT) { e_next = Erow[(t + 1) * NN + tid]; Mn = Mrow[t + 1]; }

        // renorm application (staged at t-1 = 0,4,8,...)
        float rescale = 1.0f;
        if (((t - 1) & 3) == 0) {
            uint4 u0 = *reinterpret_cast<const uint4*>(redu);
            uint4 u1 = *reinterpret_cast<const uint4*>(redu + 4);
            unsigned pm = max(max(max(u0.x, u0.y), max(u0.z, u0.w)),
                              max(max(u1.x, u1.y), max(u1.z, u1.w)));
            int e2 = (int)(pm >> 23) - 127;            // exponent of block-max p
            rescale = __uint_as_float((unsigned)(127 - e2) << 23);   // 2^-e2 (exact)
            mhat += (float)e2 * LN2_F;
        }

        // matvec partials over i-range [128*ib, 128*ib+128) from psm[cur]
        const float4* p4 = reinterpret_cast<const float4*>(psm + cur * NN + 128 * ib);
        __nv_bfloat162 c0a = bzero, c0b = bzero, c1a = bzero, c1b = bzero;
#pragma unroll
        for (int q = 0; q < 16; q++) {
            float4 v = p4[q];
            const __nv_bfloat162* pv = reinterpret_cast<const __nv_bfloat162*>(&v);
            c0a = __hfma2(a0[4 * q + 0], pv[0], c0a);
            c1a = __hfma2(a1[4 * q + 0], pv[0], c1a);
            c0b = __hfma2(a0[4 * q + 1], pv[1], c0b);
            c1b = __hfma2(a1[4 * q + 1], pv[1], c1b);
            c0a = __hfma2(a0[4 * q + 2], pv[2], c0a);
            c1a = __hfma2(a1[4 * q + 2], pv[2], c1a);
            c0b = __hfma2(a0[4 * q + 3], pv[3], c0b);
            c1b = __hfma2(a1[4 * q + 3], pv[3], c1b);
        }
        float2 f0 = __bfloat1622float2(__hadd2(c0a, c0b));
        float2 f1 = __bfloat1622float2(__hadd2(c1a, c1b));
        float S0 = f0.x + f0.y, S1 = f1.x + f1.y;
        S0 += __shfl_xor_sync(0xffffffffu, S0, 1);     // combine i-halves
        S1 += __shfl_xor_sync(0xffffffffu, S1, 1);
        float S = ib ? S1 : S0;

        p = __expf(e - Mt) * S * rescale;              // no log, no max reduction
        mhat += Mt;

        if ((t & 3) == 0) {                            // stage renorm for step t+1
            unsigned pb = __reduce_max_sync(0xffffffffu, __float_as_uint(p));
            if (lane == 0) redu[wid] = pb;
        }
        psm[(cur ^ 1) * NN + tid] = __float2bfloat16(p);
        __syncthreads();                               // ONE barrier per step
        cur ^= 1;
    }

    // log_prop[b] = mhat + log(sum_j p_j)
    float s = p;
#pragma unroll
    for (int o = 16; o; o >>= 1) s += __shfl_xor_sync(0xffffffffu, s, o);
    if (lane == 0) red[wid] = s;
    __syncthreads();
    if (tid == 0) {
        float tot = 0.f;
#pragma unroll
        for (int w = 0; w < 8; w++) tot += red[w];
        logprop_g[b] = mhat + __logf(tot);
    }
}

// ---------------- final: sum log_props over batch ----------------
__global__ void finalize_kernel(float* __restrict__ out) {
    __shared__ float red[2];
    int t = threadIdx.x;
    float v = logprop_g[t];
#pragma unroll
    for (int o = 16; o; o >>= 1) v += __shfl_xor_sync(0xffffffffu, v, o);
    if ((t & 31) == 0) red[t >> 5] = v;
    __syncthreads();
    if (t == 0) out[0] = red[0] + red[1];
}

// ---------------- launch ----------------
extern "C" void kernel_launch(void* const* d_in, const int* in_sizes, int n_in,
                              void* d_out, int out_size) {
    (void)in_sizes; (void)n_in; (void)out_size;
    const float* X     = (const float*)d_in[0];
    const float* mu    = (const float*)d_in[1];
    const float* lv    = (const float*)d_in[2];
    const float* trans = (const float*)d_in[3];
    const float* pri   = (const float*)d_in[4];
    float* out = (float*)d_out;

    prep_all<<<257, 256>>>(trans, pri, mu, lv);
    emis_kernel<<<(BB * TT) / 32, 256>>>(X);
    forward_rec<<<BB, 256>>>();
    finalize_kernel<<<1, 64>>>(out);
}